// round 7
// baseline (speedup 1.0000x reference)
#include <cuda_runtime.h>
#include <cuda_bf16.h>
#include <cstdint>

// BS=64, G=64, L=100, D=64. NG=4096 groups.
// softmax shift-invariance: V_last/V_avg/b cancel => attn = softmax_l(seqs[l].(W2@p)).
// lens, W1, W3, b unused.
// Pipeline: groups split into 2 chunks; attn(chunk k) on legacy stream,
// mlp(chunk k) on side stream overlapping attn(chunk k+1).

#define NG   4096
#define L    100
#define D    64
#define NCHUNK 2
#define GPC  (NG / NCHUNK)        // groups per chunk

__device__ float g_weighted[NG * D];     // attention-pooled rows

// ---------------------------------------------------------------------------
// helpers
// ---------------------------------------------------------------------------
__device__ __forceinline__ void cp16(unsigned int s_addr, const void* g) {
    asm volatile("cp.async.cg.shared.global [%0], [%1], 16;\n" :: "r"(s_addr), "l"(g));
}
#define CP_COMMIT() asm volatile("cp.async.commit_group;\n" ::: "memory")
#define CP_WAIT(n)  asm volatile("cp.async.wait_group %0;\n" :: "n"(n) : "memory")

__device__ __forceinline__ unsigned long long pk2(float v) {
    unsigned long long r;
    asm("mov.b64 %0, {%1, %1};" : "=l"(r) : "f"(v));
    return r;
}
__device__ __forceinline__ void fma2(unsigned long long& d,
                                     unsigned long long a, unsigned long long b) {
    asm("fma.rn.f32x2 %0, %1, %2, %0;" : "+l"(d) : "l"(a), "l"(b));
}
__device__ __forceinline__ float2 unpk(unsigned long long v) {
    float2 r;
    asm("mov.b64 {%0, %1}, %2;" : "=f"(r.x), "=f"(r.y) : "l"(v));
    return r;
}

// ---------------------------------------------------------------------------
// Kernel 1: attention pooling, 2 groups per block, 256 threads.
// Tile in registers: thread t, chunk k: row=(t>>4)+8k, cols [4*(t&15),+4).
// q = W2@p computed once per block from coalesced-staged W2 in shared.
// ---------------------------------------------------------------------------
__global__ __launch_bounds__(256) void attn_kernel(
    const float* __restrict__ seqs, const float* __restrict__ W2,
    const float* __restrict__ p, int g_base)
{
    __shared__ float w2s[D * 65];        // stride 65: q-read conflict-free
    __shared__ float ps[D];
    __shared__ float q_s[D];
    __shared__ float attn_sh[2][104];
    __shared__ float red[2][4];
    __shared__ float part4[2][4][16][4];

    const int tid  = threadIdx.x;
    const int half = tid >> 7;
    const int t    = tid & 127;
    const int g    = g_base + blockIdx.x * 2 + half;
    const int w    = t >> 5;
    const int lane = t & 31;
    const int c4   = t & 15;
    const int grp  = t >> 4;             // row group 0..7

    // ---- issue tile loads into registers (latency starts now) ----
    const float4* src = (const float4*)(seqs + (size_t)g * (L * D));
    float4 r[13];
#pragma unroll
    for (int k = 0; k < 13; ++k) {
        int idx = t + k * 128;
        if (idx < L * (D / 4)) r[k] = __ldg(src + idx);
        else                   r[k] = make_float4(0.f, 0.f, 0.f, 0.f);
    }

    // ---- coalesced stage of W2 (1024 float4) and p into shared ----
#pragma unroll
    for (int i = 0; i < 4; ++i) {
        int idx = tid + i * 256;          // < 1024
        float4 wv = __ldg((const float4*)W2 + idx);
        int row = idx >> 4, c = idx & 15;
        float* dst = &w2s[row * 65 + c * 4];
        dst[0] = wv.x; dst[1] = wv.y; dst[2] = wv.z; dst[3] = wv.w;
    }
    if (tid >= 64 && tid < 128) ps[tid - 64] = __ldg(p + tid - 64);
    __syncthreads();

    // ---- q[d] = row_d(W2) . p  (conflict-free smem) ----
    if (tid < D) {
        float acc = 0.f;
        const float* row = &w2s[tid * 65];
#pragma unroll 16
        for (int e = 0; e < D; ++e) acc += row[e] * ps[e];
        q_s[tid] = acc;
    }
    __syncthreads();

    // ---- emb: per-thread partial dot + 16-lane segmented shfl reduce ----
    const float4 q4 = *(const float4*)&q_s[c4 * 4];
#pragma unroll
    for (int k = 0; k < 13; ++k) {
        float v = r[k].x * q4.x + r[k].y * q4.y + r[k].z * q4.z + r[k].w * q4.w;
        v += __shfl_xor_sync(0xffffffffu, v, 1);
        v += __shfl_xor_sync(0xffffffffu, v, 2);
        v += __shfl_xor_sync(0xffffffffu, v, 4);
        v += __shfl_xor_sync(0xffffffffu, v, 8);
        int row = grp + 8 * k;
        if (c4 == 0 && row < L) attn_sh[half][row] = v;
    }
    __syncthreads();

    // ---- softmax over L=100 (per half: 4 warps) ----
    float v = (t < L) ? attn_sh[half][t] : -1e30f;
    float m = v;
#pragma unroll
    for (int o = 16; o > 0; o >>= 1) m = fmaxf(m, __shfl_xor_sync(0xffffffffu, m, o));
    if (lane == 0) red[half][w] = m;
    __syncthreads();
    float vmax = fmaxf(fmaxf(red[half][0], red[half][1]),
                       fmaxf(red[half][2], red[half][3]));
    __syncthreads();

    float e = (t < L) ? __expf(v - vmax) : 0.f;
    float sv = e;
#pragma unroll
    for (int o = 16; o > 0; o >>= 1) sv += __shfl_xor_sync(0xffffffffu, sv, o);
    if (lane == 0) red[half][w] = sv;
    __syncthreads();
    float inv = 1.f / (red[half][0] + red[half][1] + red[half][2] + red[half][3]);
    if (t < L) attn_sh[half][t] = e * inv;
    else if (t < 104) attn_sh[half][t] = 0.f;
    __syncthreads();

    // ---- pooling in registers ----
    float4 p4 = make_float4(0.f, 0.f, 0.f, 0.f);
#pragma unroll
    for (int k = 0; k < 13; ++k) {
        float a = attn_sh[half][grp + 8 * k];
        p4.x += a * r[k].x; p4.y += a * r[k].y;
        p4.z += a * r[k].z; p4.w += a * r[k].w;
    }
    p4.x += __shfl_xor_sync(0xffffffffu, p4.x, 16);
    p4.y += __shfl_xor_sync(0xffffffffu, p4.y, 16);
    p4.z += __shfl_xor_sync(0xffffffffu, p4.z, 16);
    p4.w += __shfl_xor_sync(0xffffffffu, p4.w, 16);
    if (lane < 16) *(float4*)&part4[half][w][lane][0] = p4;
    __syncthreads();
    if (t < D) {
        int ci = t >> 2, comp = t & 3;
        float sum = part4[half][0][ci][comp] + part4[half][1][ci][comp]
                  + part4[half][2][ci][comp] + part4[half][3][ci][comp];
        g_weighted[g * D + t] = sum;
    }
}

// ---------------------------------------------------------------------------
// MLP: out = h0 + relu(relu(h0@Wl0+bl0)@Wl1+bl1), h0 = X@Wq.
// 512 threads. 32 rows/block. K split over 2 warp-halves.
// 4 rows x 4 cols per thread; accumulators packed f32x2 (column pairs).
// ---------------------------------------------------------------------------
template<int K, bool RELU, bool BIAS, bool RESID, bool GSTORE>
__device__ __forceinline__ void gemm_stage(
    const float* __restrict__ xb, const float* __restrict__ ws,
    const float* __restrict__ bias, const float* __restrict__ resid,
    float* __restrict__ obuf, float* __restrict__ part,
    int kh, int r0, int c0, int grow0)
{
    unsigned long long acc[4][2];
#pragma unroll
    for (int i = 0; i < 4; ++i) { acc[i][0] = 0ull; acc[i][1] = 0ull; }

    const int dbase = kh * (K / 2);
#pragma unroll 4
    for (int d = 0; d < K / 2; ++d) {
        const int dd = dbase + d;
        const unsigned long long* wp =
            (const unsigned long long*)&ws[dd * 128 + c0];
        unsigned long long b0 = wp[0], b1 = wp[1];   // {wv0,wv1},{wv2,wv3}
#pragma unroll
        for (int i = 0; i < 4; ++i) {
            unsigned long long xd = pk2(xb[(r0 + i) * K + dd]);  // bcast LDS
            fma2(acc[i][0], xd, b0);
            fma2(acc[i][1], xd, b1);
        }
    }

    if (kh) {
#pragma unroll
        for (int i = 0; i < 4; ++i) {
            float2 a = unpk(acc[i][0]), b = unpk(acc[i][1]);
            *(float4*)&part[(r0 + i) * 128 + c0] = make_float4(a.x, a.y, b.x, b.y);
        }
    }
    __syncthreads();
    if (!kh) {
        float4 bv = make_float4(0.f, 0.f, 0.f, 0.f);
        if (BIAS) bv = __ldg((const float4*)&bias[c0]);
#pragma unroll
        for (int i = 0; i < 4; ++i) {
            float4 pv = *(const float4*)&part[(r0 + i) * 128 + c0];
            float2 a = unpk(acc[i][0]), b = unpk(acc[i][1]);
            float4 o = make_float4(a.x + pv.x + bv.x, a.y + pv.y + bv.y,
                                   b.x + pv.z + bv.z, b.y + pv.w + bv.w);
            if (RELU) {
                o.x = fmaxf(o.x, 0.f); o.y = fmaxf(o.y, 0.f);
                o.z = fmaxf(o.z, 0.f); o.w = fmaxf(o.w, 0.f);
            }
            if (RESID) {
                const float* rr = &resid[(r0 + i) * 128 + c0];
                o.x += rr[0]; o.y += rr[1]; o.z += rr[2]; o.w += rr[3];
            }
            if (GSTORE)
                *(float4*)&obuf[(size_t)(grow0 + r0 + i) * 128 + c0] = o;
            else
                *(float4*)&obuf[(r0 + i) * 128 + c0] = o;
        }
    }
}

__global__ __launch_bounds__(512) void mlp_kernel(
    const float* __restrict__ Wq,  const float* __restrict__ Wl0,
    const float* __restrict__ bl0, const float* __restrict__ Wl1,
    const float* __restrict__ bl1, float* __restrict__ out, int row_base)
{
    extern __shared__ float smem[];
    float* sx   = smem;            // 32x64    =  2048 f
    float* sh0  = smem + 2048;     // 32x128   =  4096 f
    float* sh1  = smem + 6144;     // 32x128   =  4096 f
    float* part = smem + 10240;    // 32x128   =  4096 f
    float* wq   = smem + 14336;    // 64x128   =  8192 f
    float* wl0  = smem + 22528;    // 128x128  = 16384 f
    float* wl1  = smem + 38912;    // 128x128  = 16384 f  (55296 f = 216 KB)

    const int t    = threadIdx.x;
    const int row0 = row_base + blockIdx.x * 32;

    const unsigned int sb = (unsigned int)__cvta_generic_to_shared(smem);

    // ---- async staging: G0 = sx + Wq, G1 = Wl0, G2 = Wl1 ----
    {
        const float4* xs = (const float4*)(g_weighted + (size_t)row0 * D);
        cp16(sb + (0 + t * 4) * 4, xs + t);                    // 512 f4
#pragma unroll
        for (int i = 0; i < 4; ++i) {
            int idx = t + i * 512;                             // 2048 f4
            cp16(sb + (14336 + idx * 4) * 4, (const float4*)Wq + idx);
        }
        CP_COMMIT();
#pragma unroll
        for (int i = 0; i < 8; ++i) {
            int idx = t + i * 512;                             // 4096 f4
            cp16(sb + (22528 + idx * 4) * 4, (const float4*)Wl0 + idx);
        }
        CP_COMMIT();
#pragma unroll
        for (int i = 0; i < 8; ++i) {
            int idx = t + i * 512;
            cp16(sb + (38912 + idx * 4) * 4, (const float4*)Wl1 + idx);
        }
        CP_COMMIT();
    }

    const int wr   = t >> 5;          // warp 0..15
    const int kh   = wr >> 3;         // K-half
    const int wh   = wr & 7;          // row-tile within half
    const int r0   = wh * 4;          // rows [r0, r0+4)
    const int c0   = (t & 31) * 4;    // cols [c0, c0+4)

    // ---- stage 1: h0 = X @ Wq  (K=64, no bias/relu) ----
    CP_WAIT(2);
    __syncthreads();
    gemm_stage<64, false, false, false, false>(sx, wq, nullptr, nullptr,
                                               sh0, part, kh, r0, c0, 0);

    // ---- stage 2: h1 = relu(h0 @ Wl0 + bl0) ----
    CP_WAIT(1);
    __syncthreads();
    gemm_stage<128, true, true, false, false>(sh0, wl0, bl0, nullptr,
                                              sh1, part, kh, r0, c0, 0);

    // ---- stage 3: out = h0 + relu(h1 @ Wl1 + bl1) ----
    CP_WAIT(0);
    __syncthreads();
    gemm_stage<128, true, true, true, true>(sh1, wl1, bl1, sh0,
                                            out, part, kh, r0, c0, row0);
}

// ---------------------------------------------------------------------------
extern "C" void kernel_launch(void* const* d_in, const int* in_sizes, int n_in,
                              void* d_out, int out_size) {
    const float* seqs = (const float*)d_in[0];
    const float* W2   = (const float*)d_in[3];
    const float* p    = (const float*)d_in[6];
    const float* Wq   = (const float*)d_in[7];
    const float* Wl0  = (const float*)d_in[8];
    const float* bl0  = (const float*)d_in[9];
    const float* Wl1  = (const float*)d_in[10];
    const float* bl1  = (const float*)d_in[11];
    float* out = (float*)d_out;

    static cudaStream_t s1 = nullptr;
    static cudaEvent_t evFork, evJoin, evChunk[NCHUNK];
    static bool init_done = false;
    if (!init_done) {
        cudaFuncSetAttribute(mlp_kernel,
                             cudaFuncAttributeMaxDynamicSharedMemorySize, 221184);
        cudaStreamCreateWithFlags(&s1, cudaStreamNonBlocking);
        cudaEventCreateWithFlags(&evFork, cudaEventDisableTiming);
        cudaEventCreateWithFlags(&evJoin, cudaEventDisableTiming);
        for (int c = 0; c < NCHUNK; ++c)
            cudaEventCreateWithFlags(&evChunk[c], cudaEventDisableTiming);
        init_done = true;
    }

    // fork side stream from the (possibly capturing) main stream
    cudaEventRecord(evFork, 0);
    cudaStreamWaitEvent(s1, evFork, 0);

    for (int c = 0; c < NCHUNK; ++c) {
        attn_kernel<<<GPC / 2, 256>>>(seqs, W2, p, c * GPC);
        cudaEventRecord(evChunk[c], 0);
        cudaStreamWaitEvent(s1, evChunk[c], 0);
        mlp_kernel<<<GPC / 32, 512, 221184, s1>>>(Wq, Wl0, bl0, Wl1, bl1,
                                                  out, c * GPC);
    }

    // join side stream back into the main stream
    cudaEventRecord(evJoin, s1);
    cudaStreamWaitEvent(0, evJoin, 0);
}